// round 6
// baseline (speedup 1.0000x reference)
#include <cuda_runtime.h>
#include <cuda_bf16.h>
#include <mma.h>
#include <math.h>

using namespace nvcuda;

#define TPB  256
#define BM   128
#define BN   128
#define BKT  16
#define LDK  24    // BKT + 8 pad -> 48B row stride, conflict-free ldmatrix
#define LDNB 136   // BN + 8 pad for NN B tile

// Scratch (allocation-free: __device__ globals)
__device__ float g_qkv[2048 * 12288];            // ~96 MB   [S, 3H]
__device__ float g_scores[134217728];            // 512 MB   [32, 2048, 2048]
__device__ float g_attn[2048 * 4096];            // 32 MB    [S, H] (heads concat)

// ---------------------------------------------------------------------------
// Generic NT GEMM with bf16 split precision (3-product emulation of fp32):
//   C[m,n] = alpha * sum_k A[m,k] * B[n,k]
// Batched over blockIdx.z via element offsets; optional causal block skip.
// ---------------------------------------------------------------------------
__global__ __launch_bounds__(TPB) void gemm_nt_split(
    const float* __restrict__ A0, int lda, long long aOff,
    const float* __restrict__ B0, int ldb, long long bOff,
    float* __restrict__ C0, int ldc, long long cOff,
    int K, float alpha, int causal)
{
    const int bn = blockIdx.x, bm = blockIdx.y, z = blockIdx.z;
    if (causal && bn > bm) return;

    const float* A = A0 + (long long)z * aOff;
    const float* B = B0 + (long long)z * bOff;
    float*       C = C0 + (long long)z * cOff;

    __shared__ __nv_bfloat16 Ah[2][BM][LDK], Al[2][BM][LDK];
    __shared__ __nv_bfloat16 Bh[2][BN][LDK], Bl[2][BN][LDK];

    const int tid = threadIdx.x;
    const int r0  = tid >> 2;          // 0..63
    const int c0  = (tid & 3) * 4;     // 0,4,8,12

    const float* Abase = A + (size_t)(bm * BM + r0) * lda + c0;
    const float* Bbase = B + (size_t)(bn * BN + r0) * ldb + c0;

    const int wid = tid >> 5;
    const int wr  = wid >> 2;          // 0..1  (64 rows each)
    const int wc  = wid & 3;           // 0..3  (32 cols each)

    wmma::fragment<wmma::accumulator, 16, 16, 16, float> fc[4][2];
#pragma unroll
    for (int i = 0; i < 4; i++)
#pragma unroll
        for (int j = 0; j < 2; j++)
            wmma::fill_fragment(fc[i][j], 0.0f);

    auto gload = [&](const float* base, int ld, int kt, float4& v0, float4& v1) {
        const float* p = base + (size_t)kt * BKT;
        v0 = *reinterpret_cast<const float4*>(p);
        v1 = *reinterpret_cast<const float4*>(p + (size_t)64 * ld);
    };
    auto sstore = [&](__nv_bfloat16 (*Hi)[LDK], __nv_bfloat16 (*Lo)[LDK],
                      const float4& v0, const float4& v1) {
        const float* f0 = reinterpret_cast<const float*>(&v0);
        const float* f1 = reinterpret_cast<const float*>(&v1);
#pragma unroll
        for (int i = 0; i < 4; i++) {
            float f = f0[i];
            __nv_bfloat16 h = __float2bfloat16(f);
            Hi[r0][c0 + i] = h;
            Lo[r0][c0 + i] = __float2bfloat16(f - __bfloat162float(h));
            f = f1[i];
            h = __float2bfloat16(f);
            Hi[r0 + 64][c0 + i] = h;
            Lo[r0 + 64][c0 + i] = __float2bfloat16(f - __bfloat162float(h));
        }
    };

    float4 a0, a1, b0, b1;
    gload(Abase, lda, 0, a0, a1);
    gload(Bbase, ldb, 0, b0, b1);
    sstore(Ah[0], Al[0], a0, a1);
    sstore(Bh[0], Bl[0], b0, b1);
    __syncthreads();

    const int ktiles = K / BKT;
    for (int kt = 0; kt < ktiles; kt++) {
        const int  buf  = kt & 1;
        const bool more = (kt + 1 < ktiles);
        float4 na0, na1, nb0, nb1;
        if (more) {
            gload(Abase, lda, kt + 1, na0, na1);
            gload(Bbase, ldb, kt + 1, nb0, nb1);
        }

        wmma::fragment<wmma::matrix_b, 16, 16, 16, __nv_bfloat16, wmma::col_major> fbh[2], fbl[2];
#pragma unroll
        for (int j = 0; j < 2; j++) {
            wmma::load_matrix_sync(fbh[j], &Bh[buf][wc * 32 + j * 16][0], LDK);
            wmma::load_matrix_sync(fbl[j], &Bl[buf][wc * 32 + j * 16][0], LDK);
        }
#pragma unroll
        for (int i = 0; i < 4; i++) {
            wmma::fragment<wmma::matrix_a, 16, 16, 16, __nv_bfloat16, wmma::row_major> fah, fal;
            wmma::load_matrix_sync(fah, &Ah[buf][wr * 64 + i * 16][0], LDK);
            wmma::load_matrix_sync(fal, &Al[buf][wr * 64 + i * 16][0], LDK);
#pragma unroll
            for (int j = 0; j < 2; j++) {
                wmma::mma_sync(fc[i][j], fah, fbh[j], fc[i][j]);
                wmma::mma_sync(fc[i][j], fah, fbl[j], fc[i][j]);
                wmma::mma_sync(fc[i][j], fal, fbh[j], fc[i][j]);
            }
        }

        if (more) {
            sstore(Ah[buf ^ 1], Al[buf ^ 1], na0, na1);
            sstore(Bh[buf ^ 1], Bl[buf ^ 1], nb0, nb1);
        }
        __syncthreads();
    }

#pragma unroll
    for (int i = 0; i < 4; i++) {
#pragma unroll
        for (int j = 0; j < 2; j++) {
#pragma unroll
            for (int e = 0; e < fc[i][j].num_elements; e++) fc[i][j].x[e] *= alpha;
            float* cp = C + (size_t)(bm * BM + wr * 64 + i * 16) * ldc
                          + bn * BN + wc * 32 + j * 16;
            wmma::store_matrix_sync(cp, fc[i][j], ldc, wmma::mem_row_major);
        }
    }
}

// ---------------------------------------------------------------------------
// Causal row softmax: one warp per row; reads cols [0, r], zero-fills up to
// the next 128 boundary so the PV GEMM never reads uninitialized scores.
// ---------------------------------------------------------------------------
__global__ __launch_bounds__(256) void softmax_causal()
{
    const int row  = blockIdx.x * 8 + (threadIdx.x >> 5);
    const int lane = threadIdx.x & 31;
    const int h = row >> 11;
    const int r = row & 2047;
    float* S = g_scores + (size_t)h * 2048 * 2048 + (size_t)r * 2048;
    const int L = r + 1;

    float vals[64];
    float m = -INFINITY;
#pragma unroll
    for (int i = 0; i < 64; i++) {
        const int c = lane + i * 32;
        float v = (c < L) ? S[c] : -INFINITY;
        vals[i] = v;
        m = fmaxf(m, v);
    }
#pragma unroll
    for (int o = 16; o > 0; o >>= 1) m = fmaxf(m, __shfl_xor_sync(0xffffffffu, m, o));

    float s = 0.0f;
#pragma unroll
    for (int i = 0; i < 64; i++) {
        float e = __expf(vals[i] - m);   // -inf lanes -> exp = 0
        vals[i] = e;
        s += e;
    }
#pragma unroll
    for (int o = 16; o > 0; o >>= 1) s += __shfl_xor_sync(0xffffffffu, s, o);

    const float inv = 1.0f / s;
#pragma unroll
    for (int i = 0; i < 64; i++) {
        const int c = lane + i * 32;
        if (c < L) S[c] = vals[i] * inv;
    }
    const int Lpad = ((r >> 7) + 1) << 7;
    for (int c = L + lane; c < Lpad; c += 32) S[c] = 0.0f;
}

// ---------------------------------------------------------------------------
// PV GEMM (NN), causal K truncation: O_h[m,d] = sum_{k<=(bm+1)*128} P[m,k]*V[k,d]
// ---------------------------------------------------------------------------
__global__ __launch_bounds__(TPB) void gemm_nn_pv()
{
    const int bm = blockIdx.y, z = blockIdx.z;
    const float* A = g_scores + (size_t)z * 4194304;       // lda = 2048
    const float* B = g_qkv + 8192 + (size_t)z * 128;       // ldb = 12288 (V head z)
    float*       C = g_attn + (size_t)z * 128;             // ldc = 4096

    __shared__ __nv_bfloat16 Ah[2][BM][LDK], Al[2][BM][LDK];
    __shared__ __nv_bfloat16 Bh[2][BKT][LDNB], Bl[2][BKT][LDNB];

    const int tid = threadIdx.x;
    const int ar = tid >> 2, ac = (tid & 3) * 4;
    const float* Abase = A + (size_t)(bm * BM + ar) * 2048 + ac;
    const int br = tid >> 5, bc = (tid & 31) * 4;
    const float* Bbase = B + (size_t)br * 12288 + bc;

    const int wid = tid >> 5, wr = wid >> 2, wc = wid & 3;
    wmma::fragment<wmma::accumulator, 16, 16, 16, float> fc[4][2];
#pragma unroll
    for (int i = 0; i < 4; i++)
#pragma unroll
        for (int j = 0; j < 2; j++)
            wmma::fill_fragment(fc[i][j], 0.0f);

    auto gloadA = [&](int kt, float4& v0, float4& v1) {
        const float* p = Abase + (size_t)kt * BKT;
        v0 = *reinterpret_cast<const float4*>(p);
        v1 = *reinterpret_cast<const float4*>(p + (size_t)64 * 2048);
    };
    auto gloadB = [&](int kt, float4& v0, float4& v1) {
        const float* p = Bbase + (size_t)kt * BKT * 12288;
        v0 = *reinterpret_cast<const float4*>(p);
        v1 = *reinterpret_cast<const float4*>(p + (size_t)8 * 12288);
    };
    auto sstoreA = [&](int buf, const float4& v0, const float4& v1) {
        const float* f0 = reinterpret_cast<const float*>(&v0);
        const float* f1 = reinterpret_cast<const float*>(&v1);
#pragma unroll
        for (int i = 0; i < 4; i++) {
            float f = f0[i];
            __nv_bfloat16 h = __float2bfloat16(f);
            Ah[buf][ar][ac + i] = h;
            Al[buf][ar][ac + i] = __float2bfloat16(f - __bfloat162float(h));
            f = f1[i];
            h = __float2bfloat16(f);
            Ah[buf][ar + 64][ac + i] = h;
            Al[buf][ar + 64][ac + i] = __float2bfloat16(f - __bfloat162float(h));
        }
    };
    auto sstoreB = [&](int buf, const float4& v0, const float4& v1) {
        const float* f0 = reinterpret_cast<const float*>(&v0);
        const float* f1 = reinterpret_cast<const float*>(&v1);
#pragma unroll
        for (int i = 0; i < 4; i++) {
            float f = f0[i];
            __nv_bfloat16 h = __float2bfloat16(f);
            Bh[buf][br][bc + i] = h;
            Bl[buf][br][bc + i] = __float2bfloat16(f - __bfloat162float(h));
            f = f1[i];
            h = __float2bfloat16(f);
            Bh[buf][br + 8][bc + i] = h;
            Bl[buf][br + 8][bc + i] = __float2bfloat16(f - __bfloat162float(h));
        }
    };

    float4 a0, a1, b0, b1;
    gloadA(0, a0, a1);
    gloadB(0, b0, b1);
    sstoreA(0, a0, a1);
    sstoreB(0, b0, b1);
    __syncthreads();

    const int ktiles = (bm + 1) * 8;   // causal: k-blocks 0..bm only
    for (int kt = 0; kt < ktiles; kt++) {
        const int  buf  = kt & 1;
        const bool more = (kt + 1 < ktiles);
        float4 na0, na1, nb0, nb1;
        if (more) { gloadA(kt + 1, na0, na1); gloadB(kt + 1, nb0, nb1); }

        wmma::fragment<wmma::matrix_b, 16, 16, 16, __nv_bfloat16, wmma::row_major> fbh[2], fbl[2];
#pragma unroll
        for (int j = 0; j < 2; j++) {
            wmma::load_matrix_sync(fbh[j], &Bh[buf][0][wc * 32 + j * 16], LDNB);
            wmma::load_matrix_sync(fbl[j], &Bl[buf][0][wc * 32 + j * 16], LDNB);
        }
#pragma unroll
        for (int i = 0; i < 4; i++) {
            wmma::fragment<wmma::matrix_a, 16, 16, 16, __nv_bfloat16, wmma::row_major> fah, fal;
            wmma::load_matrix_sync(fah, &Ah[buf][wr * 64 + i * 16][0], LDK);
            wmma::load_matrix_sync(fal, &Al[buf][wr * 64 + i * 16][0], LDK);
#pragma unroll
            for (int j = 0; j < 2; j++) {
                wmma::mma_sync(fc[i][j], fah, fbh[j], fc[i][j]);
                wmma::mma_sync(fc[i][j], fah, fbl[j], fc[i][j]);
                wmma::mma_sync(fc[i][j], fal, fbh[j], fc[i][j]);
            }
        }

        if (more) { sstoreA(buf ^ 1, na0, na1); sstoreB(buf ^ 1, nb0, nb1); }
        __syncthreads();
    }

#pragma unroll
    for (int i = 0; i < 4; i++)
#pragma unroll
        for (int j = 0; j < 2; j++) {
            float* cp = C + (size_t)(bm * BM + wr * 64 + i * 16) * 4096
                          + wc * 32 + j * 16;
            wmma::store_matrix_sync(cp, fc[i][j], 4096, wmma::mem_row_major);
        }
}

// ---------------------------------------------------------------------------
// kernel_launch: 5 sequential launches on the capture stream.
// ---------------------------------------------------------------------------
extern "C" void kernel_launch(void* const* d_in, const int* in_sizes, int n_in,
                              void* d_out, int out_size)
{
    const float* X  = (const float*)d_in[0];   // hidden_states [1,2048,4096]
    // d_in[1] = attention_mask (pure causal; applied analytically, unused)
    const float* Wp = (const float*)d_in[2];   // w_pack [12288,4096]
    const float* Wo = (const float*)d_in[3];   // w_o    [4096,4096]
    float* out = (float*)d_out;                // [2048,4096]

    float *qkv = nullptr, *scores = nullptr, *attn = nullptr;
    cudaGetSymbolAddress((void**)&qkv,    g_qkv);
    cudaGetSymbolAddress((void**)&scores, g_scores);
    cudaGetSymbolAddress((void**)&attn,   g_attn);

    // 1) qkv[2048,12288] = X @ Wp^T
    gemm_nt_split<<<dim3(96, 16, 1), TPB>>>(X, 4096, 0, Wp, 4096, 0,
                                            qkv, 12288, 0, 4096, 1.0f, 0);

    // 2) scores_h = Q_h @ K_h^T * 1/sqrt(128), lower-triangular blocks only
    gemm_nt_split<<<dim3(16, 16, 32), TPB>>>(qkv, 12288, 128,
                                             qkv + 4096, 12288, 128,
                                             scores, 2048, 4194304LL,
                                             128, 0.08838834764831845f, 1);

    // 3) causal row softmax (+ zero-fill to 128 boundary)
    softmax_causal<<<8192, 256>>>();

    // 4) attn_out_h = P_h @ V_h (causal K truncation)
    gemm_nn_pv<<<dim3(1, 16, 32), TPB>>>();

    // 5) out = attn_out @ Wo^T
    gemm_nt_split<<<dim3(32, 16, 1), TPB>>>(attn, 4096, 0, Wo, 4096, 0,
                                            out, 4096, 0, 4096, 1.0f, 0);
}

// round 9
// speedup vs baseline: 1.0167x; 1.0167x over previous
#include <cuda_runtime.h>
#include <cuda_bf16.h>
#include <mma.h>
#include <math.h>
#include <stdint.h>

using namespace nvcuda;

#define TPB 256

// ---------------------------------------------------------------------------
// Persistent scratch (allocation-free __device__ globals, ~943 MB total)
// ---------------------------------------------------------------------------
__device__ __nv_bfloat16 g_xhi [2048*4096],  g_xlo [2048*4096];    // 16MB each
__device__ __nv_bfloat16 g_wphi[12288*4096], g_wplo[12288*4096];   // 100MB each
__device__ __nv_bfloat16 g_wohi[4096*4096],  g_wolo[4096*4096];    // 33.5MB each
__device__ __nv_bfloat16 g_qhi [2048*12288], g_qlo [2048*12288];   // 50MB each (qkv split)
__device__ float         g_scores[134217728];                      // 512MB fp32 logits,
                                                                   // reused in-place as split-bf16 P
__device__ __nv_bfloat16 g_ahi [2048*4096],  g_alo [2048*4096];    // 16MB each (attn split)

// ---------------------------------------------------------------------------
// cp.async helpers
// ---------------------------------------------------------------------------
__device__ __forceinline__ void cp16(uint32_t s, const void* g) {
    asm volatile("cp.async.cg.shared.global [%0], [%1], 16;" :: "r"(s), "l"(g));
}
__device__ __forceinline__ void cp_commit() { asm volatile("cp.async.commit_group;"); }
__device__ __forceinline__ void cp_wait1()  { asm volatile("cp.async.wait_group 1;"); }
__device__ __forceinline__ void cp_wait0()  { asm volatile("cp.async.wait_group 0;"); }

// ---------------------------------------------------------------------------
// fp32 -> (hi, lo) bf16 split converter (vectorized, one-shot per array)
// ---------------------------------------------------------------------------
__global__ __launch_bounds__(256) void split_convert(
    const float* __restrict__ in,
    __nv_bfloat16* __restrict__ hi, __nv_bfloat16* __restrict__ lo, int n)
{
    int i = (blockIdx.x * 256 + threadIdx.x) * 4;
    if (i >= n) return;
    float4 v = *reinterpret_cast<const float4*>(in + i);
    float f[4] = {v.x, v.y, v.z, v.w};
    __nv_bfloat16 h[4], l[4];
#pragma unroll
    for (int t = 0; t < 4; t++) {
        h[t] = __float2bfloat16(f[t]);
        l[t] = __float2bfloat16(f[t] - __bfloat162float(h[t]));
    }
    __nv_bfloat162 ph0, ph1, pl0, pl1;
    ph0.x = h[0]; ph0.y = h[1]; ph1.x = h[2]; ph1.y = h[3];
    pl0.x = l[0]; pl0.y = l[1]; pl1.x = l[2]; pl1.y = l[3];
    *reinterpret_cast<__nv_bfloat162*>(hi + i)     = ph0;
    *reinterpret_cast<__nv_bfloat162*>(hi + i + 2) = ph1;
    *reinterpret_cast<__nv_bfloat162*>(lo + i)     = pl0;
    *reinterpret_cast<__nv_bfloat162*>(lo + i + 2) = pl1;
}

// ---------------------------------------------------------------------------
// Shared epilogue helper: per-warp split-bf16 output conversion through a
// small smem staging region (16x16 fp32 per warp).
// ---------------------------------------------------------------------------
__device__ __forceinline__ void epilogue_split(
    char* smem_raw,
    wmma::fragment<wmma::accumulator, 16, 16, 16, float> (&fc)[4][2],
    __nv_bfloat16* CH, __nv_bfloat16* CL,
    int ldc, size_t row0, size_t col0, int wid, int wr, int wc, int lane)
{
    __syncthreads();                       // all warps done reading mainloop smem
    float* stg = reinterpret_cast<float*>(smem_raw) + wid * 256;   // 16x16 fp32
    const int rr = lane >> 1, cc = (lane & 1) * 8;
#pragma unroll
    for (int i = 0; i < 4; i++) {
#pragma unroll
        for (int j = 0; j < 2; j++) {
            wmma::store_matrix_sync(stg, fc[i][j], 16, wmma::mem_row_major);
            __syncwarp();
            const float* src = stg + rr * 16 + cc;
            __nv_bfloat16 hv[8], lv[8];
#pragma unroll
            for (int t = 0; t < 8; t++) {
                const float f = src[t];
                hv[t] = __float2bfloat16(f);
                lv[t] = __float2bfloat16(f - __bfloat162float(hv[t]));
            }
            const size_t go = (row0 + wr * 64 + i * 16 + rr) * (size_t)ldc
                            + col0 + wc * 32 + j * 16 + cc;
            *reinterpret_cast<uint4*>(CH + go) = *reinterpret_cast<const uint4*>(hv);
            *reinterpret_cast<uint4*>(CL + go) = *reinterpret_cast<const uint4*>(lv);
            __syncwarp();
        }
    }
}

// ---------------------------------------------------------------------------
// NT GEMM, split-bf16 operands, BK=16, cp.async double buffer, static smem.
// C = alpha * A·B^T via 3-product split: ah·bh + ah·bl + al·bh.
// Output: fp32 (Cf != null) or split bf16 (Chi/Clo).
// smem (48 KB exactly): sA [2buf][2term][128][24]bf16 @0 (24576 B),
//                       sB same @24576. Epilogue staging reuses @0.
// ---------------------------------------------------------------------------
__global__ __launch_bounds__(TPB) void gemm_nt(
    const __nv_bfloat16* __restrict__ Ahi, const __nv_bfloat16* __restrict__ Alo,
    int lda, long long aOff,
    const __nv_bfloat16* __restrict__ Bhi, const __nv_bfloat16* __restrict__ Blo,
    int ldb, long long bOff,
    float* __restrict__ Cf, __nv_bfloat16* __restrict__ Chi, __nv_bfloat16* __restrict__ Clo,
    int ldc, long long cOff,
    int K, float alpha, int causal)
{
    const int bn = blockIdx.x, bm = blockIdx.y, z = blockIdx.z;
    if (causal && bn > bm) return;

    Ahi += (long long)z * aOff; Alo += (long long)z * aOff;
    Bhi += (long long)z * bOff; Blo += (long long)z * bOff;

    __shared__ char smem_raw[49152];
    __nv_bfloat16* sh = reinterpret_cast<__nv_bfloat16*>(smem_raw);
    const uint32_t sbase = (uint32_t)__cvta_generic_to_shared(sh);

    const int tid  = threadIdx.x;
    const int lane = tid & 31;
    const int wid  = tid >> 5, wr = wid >> 2, wc = wid & 3;

    // per-thread load coords: 128 rows x 2 chunks of 8 elems
    const int lr = tid >> 1, lc = (tid & 1) * 8;

    auto load_tile = [&](int buf, int kt) {
        const int k0 = kt * 16;
        const size_t ga = (size_t)(bm * 128 + lr) * lda + k0 + lc;
        const size_t gb = (size_t)(bn * 128 + lr) * ldb + k0 + lc;
        const uint32_t so = (uint32_t)(buf * 12288 + (lr * 24 + lc) * 2);
        cp16(sbase + so,                Ahi + ga);
        cp16(sbase + so + 6144,         Alo + ga);   // lo term
        cp16(sbase + 24576 + so,        Bhi + gb);
        cp16(sbase + 24576 + so + 6144, Blo + gb);
    };

    wmma::fragment<wmma::accumulator, 16, 16, 16, float> fc[4][2];
#pragma unroll
    for (int i = 0; i < 4; i++)
#pragma unroll
        for (int j = 0; j < 2; j++) wmma::fill_fragment(fc[i][j], 0.0f);

    load_tile(0, 0); cp_commit();

    const int ktiles = K >> 4;
    for (int kt = 0; kt < ktiles; kt++) {
        const int buf = kt & 1;
        const bool more = (kt + 1 < ktiles);
        if (more) { load_tile(buf ^ 1, kt + 1); cp_commit(); cp_wait1(); }
        else      { cp_wait0(); }
        __syncthreads();

        const __nv_bfloat16* bufA = sh + buf * 6144;            // elems
        const __nv_bfloat16* bufB = sh + 12288 + buf * 6144;

        wmma::fragment<wmma::matrix_b, 16, 16, 16, __nv_bfloat16, wmma::col_major> fbh[2], fbl[2];
#pragma unroll
        for (int j = 0; j < 2; j++) {
            wmma::load_matrix_sync(fbh[j], bufB + (wc * 32 + j * 16) * 24, 24);
            wmma::load_matrix_sync(fbl[j], bufB + 3072 + (wc * 32 + j * 16) * 24, 24);
        }
#pragma unroll
        for (int i = 0; i < 4; i++) {
            wmma::fragment<wmma::matrix_a, 16, 16, 16, __nv_bfloat16, wmma::row_major> fah, fal;
            wmma::load_matrix_sync(fah, bufA + (wr * 64 + i * 16) * 24, 24);
            wmma::load_matrix_sync(fal, bufA + 3072 + (wr * 64 + i * 16) * 24, 24);
#pragma unroll
            for (int j = 0; j < 2; j++) {
                wmma::mma_sync(fc[i][j], fah, fbh[j], fc[i][j]);
                wmma::mma_sync(fc[i][j], fah, fbl[j], fc[i][j]);
                wmma::mma_sync(fc[i][j], fal, fbh[j], fc[i][j]);
            }
        }
        __syncthreads();
    }

    if (Cf) {
        float* C = Cf + (long long)z * cOff;
#pragma unroll
        for (int i = 0; i < 4; i++)
#pragma unroll
            for (int j = 0; j < 2; j++) {
#pragma unroll
                for (int e = 0; e < fc[i][j].num_elements; e++) fc[i][j].x[e] *= alpha;
                wmma::store_matrix_sync(
                    C + (size_t)(bm * 128 + wr * 64 + i * 16) * ldc + bn * 128 + wc * 32 + j * 16,
                    fc[i][j], ldc, wmma::mem_row_major);
            }
    } else {
        epilogue_split(smem_raw, fc,
                       Chi + (long long)z * cOff, Clo + (long long)z * cOff,
                       ldc, (size_t)bm * 128, (size_t)bn * 128, wid, wr, wc, lane);
    }
}

// ---------------------------------------------------------------------------
// NN GEMM for PV: O_h = P_h · V_h, causal K truncation, split operands,
// split output. A: in-place split P inside g_scores (row = [2048 hi | 2048 lo]
// bf16, row stride 4096). B: V head slice of split qkv.
// smem: sA [2][2][128][24] @0 (24576 B); sB [2][2][16][136] @24576 (17408 B).
// ---------------------------------------------------------------------------
__global__ __launch_bounds__(TPB) void gemm_nn(
    const __nv_bfloat16* __restrict__ Ahi, const __nv_bfloat16* __restrict__ Alo,
    int lda, long long aOff,
    const __nv_bfloat16* __restrict__ Bhi, const __nv_bfloat16* __restrict__ Blo,
    int ldb, long long bOff,
    __nv_bfloat16* __restrict__ Chi, __nv_bfloat16* __restrict__ Clo,
    int ldc, long long cOff)
{
    const int bm = blockIdx.y, z = blockIdx.z;
    Ahi += (long long)z * aOff; Alo += (long long)z * aOff;
    Bhi += (long long)z * bOff; Blo += (long long)z * bOff;

    __shared__ char smem_raw[41984];
    __nv_bfloat16* sh = reinterpret_cast<__nv_bfloat16*>(smem_raw);
    const uint32_t sbase = (uint32_t)__cvta_generic_to_shared(sh);

    const int tid  = threadIdx.x;
    const int lane = tid & 31;
    const int wid  = tid >> 5, wr = wid >> 2, wc = wid & 3;

    const int ar = tid >> 1,  ac = (tid & 1) * 8;        // A: 128r x 2 chunks
    const int br = tid >> 4,  bc = (tid & 15) * 8;       // B: 16r  x 16 chunks

    auto load_tile = [&](int buf, int kt) {
        const int k0 = kt * 16;
        {
            const size_t ga = (size_t)(bm * 128 + ar) * lda + k0 + ac;
            const uint32_t so = (uint32_t)(buf * 12288 + (ar * 24 + ac) * 2);
            cp16(sbase + so,        Ahi + ga);
            cp16(sbase + so + 6144, Alo + ga);
        }
        {
            const size_t gb = (size_t)(k0 + br) * ldb + bc;
            const uint32_t so = (uint32_t)(24576 + buf * 8704 + (br * 136 + bc) * 2);
            cp16(sbase + so,        Bhi + gb);
            cp16(sbase + so + 4352, Blo + gb);
        }
    };

    wmma::fragment<wmma::accumulator, 16, 16, 16, float> fc[4][2];
#pragma unroll
    for (int i = 0; i < 4; i++)
#pragma unroll
        for (int j = 0; j < 2; j++) wmma::fill_fragment(fc[i][j], 0.0f);

    load_tile(0, 0); cp_commit();

    const int ktiles = (bm + 1) * 8;          // causal: k < (bm+1)*128
    for (int kt = 0; kt < ktiles; kt++) {
        const int buf = kt & 1;
        const bool more = (kt + 1 < ktiles);
        if (more) { load_tile(buf ^ 1, kt + 1); cp_commit(); cp_wait1(); }
        else      { cp_wait0(); }
        __syncthreads();

        const __nv_bfloat16* bufA = sh + buf * 6144;
        const __nv_bfloat16* bufB = sh + 12288 + buf * 4352;

        wmma::fragment<wmma::matrix_b, 16, 16, 16, __nv_bfloat16, wmma::row_major> fbh[2], fbl[2];
#pragma unroll
        for (int j = 0; j < 2; j++) {
            wmma::load_matrix_sync(fbh[j], bufB + wc * 32 + j * 16, 136);
            wmma::load_matrix_sync(fbl[j], bufB + 2176 + wc * 32 + j * 16, 136);
        }
#pragma unroll
        for (int i = 0; i < 4; i++) {
            wmma::fragment<wmma::matrix_a, 16, 16, 16, __nv_bfloat16, wmma::row_major> fah, fal;
            wmma::load_matrix_sync(fah, bufA + (wr * 64 + i * 16) * 24, 24);
            wmma::load_matrix_sync(fal, bufA + 3072 + (wr * 64 + i * 16) * 24, 24);
#pragma unroll
            for (int j = 0; j < 2; j++) {
                wmma::mma_sync(fc[i][j], fah, fbh[j], fc[i][j]);
                wmma::mma_sync(fc[i][j], fah, fbl[j], fc[i][j]);
                wmma::mma_sync(fc[i][j], fal, fbh[j], fc[i][j]);
            }
        }
        __syncthreads();
    }

    epilogue_split(smem_raw, fc,
                   Chi + (long long)z * cOff, Clo + (long long)z * cOff,
                   ldc, (size_t)bm * 128, 0, wid, wr, wc, lane);
}

// ---------------------------------------------------------------------------
// Causal row softmax: fp32 logits in, split-bf16 P written IN-PLACE over the
// same row: [2048 bf16 hi | 2048 bf16 lo] (8 KB = same bytes as the fp32 row).
// All reads complete before the shfl reductions; writes after — race-free.
// Zero-fills hi/lo up to the row's 128-block boundary.
// ---------------------------------------------------------------------------
__global__ __launch_bounds__(256) void softmax_causal()
{
    const int row  = blockIdx.x * 8 + (threadIdx.x >> 5);
    const int lane = threadIdx.x & 31;
    const int hd = row >> 11;
    const int r  = row & 2047;
    float* S = g_scores + (size_t)hd * 4194304 + (size_t)r * 2048;
    __nv_bfloat16* PH = reinterpret_cast<__nv_bfloat16*>(S);
    __nv_bfloat16* PL = PH + 2048;
    const int L = r + 1;

    float vals[64];
    float m = -INFINITY;
#pragma unroll
    for (int i = 0; i < 64; i++) {
        const int c = lane + i * 32;
        float v = (c < L) ? S[c] : -INFINITY;
        vals[i] = v;
        m = fmaxf(m, v);
    }
#pragma unroll
    for (int o = 16; o > 0; o >>= 1) m = fmaxf(m, __shfl_xor_sync(0xffffffffu, m, o));

    float s = 0.0f;
#pragma unroll
    for (int i = 0; i < 64; i++) {
        float e = __expf(vals[i] - m);
        vals[i] = e;
        s += e;
    }
#pragma unroll
    for (int o = 16; o > 0; o >>= 1) s += __shfl_xor_sync(0xffffffffu, s, o);

    const float inv = 1.0f / s;
#pragma unroll
    for (int i = 0; i < 64; i++) {
        const int c = lane + i * 32;
        if (c < L) {
            const float p = vals[i] * inv;
            const __nv_bfloat16 hh = __float2bfloat16(p);
            PH[c] = hh;
            PL[c] = __float2bfloat16(p - __bfloat162float(hh));
        }
    }
    const int Lpad = ((r >> 7) + 1) << 7;
    const __nv_bfloat16 z16 = __float2bfloat16(0.0f);
    for (int c = L + lane; c < Lpad; c += 32) { PH[c] = z16; PL[c] = z16; }
}

// ---------------------------------------------------------------------------
// kernel_launch: 8 sequential launches, all static smem, no attribute calls.
// ---------------------------------------------------------------------------
extern "C" void kernel_launch(void* const* d_in, const int* in_sizes, int n_in,
                              void* d_out, int out_size)
{
    const float* X  = (const float*)d_in[0];   // hidden_states [1,2048,4096]
    // d_in[1] = attention_mask (pure causal; applied analytically, unused)
    const float* Wp = (const float*)d_in[2];   // w_pack [12288,4096]
    const float* Wo = (const float*)d_in[3];   // w_o    [4096,4096]
    float* out = (float*)d_out;                // [2048,4096] fp32

    __nv_bfloat16 *xhi, *xlo, *wphi, *wplo, *wohi, *wolo, *qhi, *qlo, *ahi, *alo;
    float* scores;
    cudaGetSymbolAddress((void**)&xhi,  g_xhi);  cudaGetSymbolAddress((void**)&xlo,  g_xlo);
    cudaGetSymbolAddress((void**)&wphi, g_wphi); cudaGetSymbolAddress((void**)&wplo, g_wplo);
    cudaGetSymbolAddress((void**)&wohi, g_wohi); cudaGetSymbolAddress((void**)&wolo, g_wolo);
    cudaGetSymbolAddress((void**)&qhi,  g_qhi);  cudaGetSymbolAddress((void**)&qlo,  g_qlo);
    cudaGetSymbolAddress((void**)&ahi,  g_ahi);  cudaGetSymbolAddress((void**)&alo,  g_alo);
    cudaGetSymbolAddress((void**)&scores, g_scores);

    // 0) split conversions (X, Wp, Wo) -> persistent bf16 hi/lo
    split_convert<<<8192,  256>>>(X,  xhi,  xlo,  8388608);
    split_convert<<<49152, 256>>>(Wp, wphi, wplo, 50331648);
    split_convert<<<16384, 256>>>(Wo, wohi, wolo, 16777216);

    // 1) qkv(split) = X @ Wp^T
    gemm_nt<<<dim3(96, 16, 1), TPB>>>(
        xhi, xlo, 4096, 0, wphi, wplo, 4096, 0,
        nullptr, qhi, qlo, 12288, 0, 4096, 1.0f, 0);

    // 2) scores_h(fp32) = Q_h @ K_h^T * 1/sqrt(128), lower-tri blocks only
    gemm_nt<<<dim3(16, 16, 32), TPB>>>(
        qhi, qlo, 12288, 128, qhi + 4096, qlo + 4096, 12288, 128,
        scores, nullptr, nullptr, 2048, 4194304LL,
        128, 0.08838834764831845f, 1);

    // 3) causal softmax: fp32 logits -> split-bf16 P in-place (+ zero-fill)
    softmax_causal<<<8192, 256>>>();

    // 4) attn(split) = P_h @ V_h (causal K truncation)
    //    A = in-place split P: row stride 4096 bf16 ([hi|lo] per row),
    //    head stride 8388608 bf16, lo plane at +2048.
    {
        const __nv_bfloat16* phi = reinterpret_cast<const __nv_bfloat16*>(scores);
        const __nv_bfloat16* plo = phi + 2048;
        gemm_nn<<<dim3(1, 16, 32), TPB>>>(
            phi, plo, 4096, 8388608LL,
            qhi + 8192, qlo + 8192, 12288, 128,
            ahi, alo, 4096, 128);
    }

    // 5) out(fp32) = attn @ Wo^T
    gemm_nt<<<dim3(32, 16, 1), TPB>>>(
        ahi, alo, 4096, 0, wohi, wolo, 4096, 0,
        out, nullptr, nullptr, 4096, 0, 4096, 1.0f, 0);
}